// round 4
// baseline (speedup 1.0000x reference)
#include <cuda_runtime.h>
#include <cuda_fp16.h>
#include <math.h>

#define N_PIX (768*768)          // 589824 pixels
#define D     256
#define C     21
#define P     64                 // pixels per tile
#define NTILES (N_PIX / P)       // 9216
#define TPB   512
#define GRID  148

// ---------------- global scratch (static, zero-initialized at load) ----------------
__device__ float    g_sums[C * D];
__device__ int      g_counts[C];
__device__ unsigned g_done;

// ---------------- bulk async copy + mbarrier helpers ----------------
__device__ __forceinline__ unsigned s2u(const void* p) {
    return (unsigned)__cvta_generic_to_shared(p);
}
__device__ __forceinline__ void bulk_cp(void* s, const void* g, unsigned bytes, unsigned mbar) {
    asm volatile("cp.async.bulk.shared::cluster.global.mbarrier::complete_tx::bytes "
                 "[%0], [%1], %2, [%3];\n"
                 :: "r"(s2u(s)), "l"(g), "r"(bytes), "r"(mbar) : "memory");
}
__device__ __forceinline__ void mbar_init(unsigned mbar, unsigned cnt) {
    asm volatile("mbarrier.init.shared.b64 [%0], %1;\n" :: "r"(mbar), "r"(cnt) : "memory");
}
__device__ __forceinline__ void mbar_expect(unsigned mbar, unsigned tx) {
    asm volatile("mbarrier.arrive.expect_tx.shared.b64 _, [%0], %1;\n"
                 :: "r"(mbar), "r"(tx) : "memory");
}
__device__ __forceinline__ void mbar_wait(unsigned mbar, unsigned ph) {
    unsigned done;
    asm volatile("{\n\t.reg .pred p;\n\t"
                 "mbarrier.try_wait.parity.acquire.cta.shared::cta.b64 p, [%1], %2;\n\t"
                 "selp.b32 %0, 1, 0, p;\n\t}"
                 : "=r"(done) : "r"(mbar), "r"(ph) : "memory");
    if (!done) {
        asm volatile("{\n\t.reg .pred P1;\n\t"
                     "WL_%=:\n\t"
                     "mbarrier.try_wait.parity.acquire.cta.shared::cta.b64 P1, [%0], %1, 0x989680;\n\t"
                     "@P1 bra.uni WD_%=;\n\t"
                     "bra.uni WL_%=;\n\t"
                     "WD_%=:\n\t}"
                     :: "r"(mbar), "r"(ph) : "memory");
    }
}

// ---------------- smem layout (floats) ----------------
// buf   : 2 * D * P   = 32768 (128 KB)  double-buffered tile [d][64]
// slab  : 2 * P       = 128            labels
// acc   : 2 * C * D   = 10752 (43 KB)  two accumulator copies
// nred  : TPB         = 512            scalar partial squares
// aux   : P           = 64             packed (lab*D)<<16 | half(invnorm)
// scnt  : 32          = 32
// mbar  : 4           = 2 x 8B mbarriers
#define SM_BUF   0
#define SM_SLAB  (2*D*P)
#define SM_ACC   (SM_SLAB + 2*P)
#define SM_NRED  (SM_ACC + 2*C*D)
#define SM_AUX   (SM_NRED + TPB)
#define SM_SCNT  (SM_AUX + P)
#define SM_MBAR  (SM_SCNT + 32)
#define SM_TOTAL_FLOATS (SM_MBAR + 8)
#define SMEM_BYTES (SM_TOTAL_FLOATS * 4)

#define TILE_TX (D * P * 4 + P * 4)   // 65536 + 256 bytes

// issue all bulk copies for tile `tile` into buffer b (threads cooperate)
__device__ __forceinline__ void issue_tile(const float* __restrict__ feat,
                                           const int* __restrict__ lab,
                                           float* buf, int* slab, unsigned mbar_b,
                                           int b, int tile, int t) {
    const int p0 = tile * P;
    if (t == 511) mbar_expect(mbar_b, TILE_TX);
    if (t < D) {          // one 256B row per dim
        bulk_cp(buf + b * (D * P) + t * P, feat + (size_t)t * N_PIX + p0, P * 4, mbar_b);
    } else if (t == D) {  // labels row
        bulk_cp(slab + b * P, lab + p0, P * 4, mbar_b);
    }
}

// ---------------- single fused kernel ----------------
__global__ __launch_bounds__(TPB, 1)
void fused_kernel(const float* __restrict__ feat, const int* __restrict__ lab,
                  const float* __restrict__ proto, float* __restrict__ out) {
    extern __shared__ float smem[];
    float*    buf  = smem + SM_BUF;
    int*      slab = (int*)(smem + SM_SLAB);
    float*    acc  = smem + SM_ACC;
    float*    nred = smem + SM_NRED;
    unsigned* aux  = (unsigned*)(smem + SM_AUX);
    int*      scnt = (int*)(smem + SM_SCNT);
    const unsigned mbar0 = s2u(smem + SM_MBAR);

    const int t = threadIdx.x;

    for (int i = t; i < 2 * C * D; i += TPB) acc[i] = 0.f;
    if (t < C) scnt[t] = 0;
    if (t == 0) {
        mbar_init(mbar0, 1);
        mbar_init(mbar0 + 8, 1);
        asm volatile("fence.proxy.async.shared::cta;\n" ::: "memory");
    }
    __syncthreads();

    int tl = blockIdx.x;
    issue_tile(feat, lab, buf, slab, mbar0, 0, tl, t);

    const int dim = t & (D - 1);     // 0..255
    const int s   = t >> 8;          // thread-set 0/1
    float* ac = acc + s * (C * D);
    const int pss = t & (P - 1);     // SS pass pixel
    const int qss = t >> 6;          // SS pass dim-octet (0..7)

    int k = 0;
    for (; tl < NTILES; tl += GRID, k++) {
        const int b  = k & 1;
        const unsigned ph = (k >> 1) & 1u;

        int nxt = tl + GRID;
        if (nxt < NTILES)
            issue_tile(feat, lab, buf, slab, mbar0 + 8 * (b ^ 1), b ^ 1, nxt, t);

        mbar_wait(mbar0 + 8 * b, ph);       // per-thread acquire wait (no bar needed)

        const float* tbase = buf + b * (D * P);
        const int*   lb    = slab + b * P;

        // ---- per-pixel sum of squares: 8 threads per pixel, 32 dims each ----
        {
            float ss = 0.f;
            #pragma unroll
            for (int dd = 0; dd < 32; dd++) {
                float v = tbase[(qss * 32 + dd) * P + pss];
                ss += v * v;
            }
            nred[t] = ss;
        }
        __syncthreads();
        if (t < P) {
            float ssum = 0.f;
            #pragma unroll
            for (int q = 0; q < 8; q++) ssum += nred[q * P + t];
            float inv = 1.0f / fmaxf(sqrtf(ssum), 1e-12f);
            int labv = lb[t];
            aux[t] = ((unsigned)(labv * D) << 16) |
                     (unsigned)__half_as_ushort(__float2half_rn(inv));
            atomicAdd(&scnt[labv], 1);
        }
        __syncthreads();

        // ---- scatter-accumulate: thread owns dim, set s owns 32 pixels ----
        {
            const float* tb = tbase + dim * P;
            #pragma unroll
            for (int i = 0; i < 32; i++) {
                int p = ((dim + i) & 31) | (s << 5);      // lane-staggered, conflict-free
                unsigned a = aux[p];
                float w = __half2float(__ushort_as_half((unsigned short)(a & 0xffffu)));
                int cb = (int)(a >> 16);                   // lab * D
                ac[cb + dim] += tb[p] * w;
            }
        }
        __syncthreads();
    }

    // ---- flush per-block partials ----
    for (int i = t; i < C * D; i += TPB)
        atomicAdd(&g_sums[i], acc[i] + acc[C * D + i]);
    if (t < C) atomicAdd(&g_counts[t], scnt[t]);
    __syncthreads();

    // ---- last block does the finalize ----
    __shared__ unsigned s_last;
    if (t == 0) {
        __threadfence();
        s_last = (atomicAdd(&g_done, 1u) == GRID - 1) ? 1u : 0u;
    }
    __syncthreads();
    if (!s_last) return;

    float* s_mean  = smem;                 // C*D
    float* s_proto = smem + C * D;         // C*D
    float* s_logit = smem + 2 * C * D;     // C*C

    for (int i = t; i < C * D; i += TPB) {
        int c = i / D;
        float cnt = (float)g_counts[c];
        s_mean[i]  = g_sums[i] / fmaxf(cnt, 1.0f);
        s_proto[i] = proto[i];
    }
    __syncthreads();

    int w = t >> 5, l = t & 31;
    for (int r = w; r < C; r += TPB / 32) {
        for (int j = 0; j < C; j++) {
            float sacc = 0.f;
            #pragma unroll
            for (int kk = 0; kk < 8; kk++)
                sacc += s_mean[r * D + l + 32 * kk] * s_proto[j * D + l + 32 * kk];
            #pragma unroll
            for (int o = 16; o; o >>= 1) sacc += __shfl_xor_sync(0xffffffffu, sacc, o);
            if (l == 0) s_logit[r * C + j] = sacc * 10.0f;   // / TEMP (0.1)
        }
    }
    __syncthreads();

    if (t < 32) {
        float v = 0.f;
        if (t >= 1 && t < C) {
            float mx = -INFINITY;
            for (int j = 0; j < C; j++) mx = fmaxf(mx, s_logit[t * C + j]);
            float den = 0.f;
            for (int j = 1; j < C; j++) den += expf(s_logit[t * C + j] - mx);
            v = logf(den) - (s_logit[t * C + t] - mx);
        }
        #pragma unroll
        for (int o = 16; o; o >>= 1) v += __shfl_xor_sync(0xffffffffu, v, o);
        if (t == 0) out[0] = v / (float)(C - 1);
    }
    __syncthreads();

    // ---- reset globals for next graph replay ----
    for (int i = t; i < C * D; i += TPB) g_sums[i] = 0.f;
    if (t < C) g_counts[t] = 0;
    if (t == 0) g_done = 0;
}

// ---------------- launch ----------------
extern "C" void kernel_launch(void* const* d_in, const int* in_sizes, int n_in,
                              void* d_out, int out_size) {
    const float* feat  = (const float*)d_in[0];   // [1,256,768,768]
    const float* proto = (const float*)d_in[1];   // [21,256]
    // d_in[2] = outputs (unused by the loss)
    const int*   lab   = (const int*)d_in[3];     // [1,1,768,768]
    float* out = (float*)d_out;

    cudaFuncSetAttribute(fused_kernel,
                         cudaFuncAttributeMaxDynamicSharedMemorySize, SMEM_BYTES);

    fused_kernel<<<GRID, TPB, SMEM_BYTES>>>(feat, lab, proto, out);
}

// round 5
// speedup vs baseline: 1.0059x; 1.0059x over previous
#include <cuda_runtime.h>
#include <cuda_fp16.h>
#include <math.h>

#define N_PIX (768*768)          // 589824 pixels
#define D     256
#define C     21
#define P     64                 // pixels per tile
#define NTILES (N_PIX / P)       // 9216
#define TPB   512
#define GRID  148

// ---------------- global scratch (static, zero-initialized at load) ----------------
__device__ float    g_sums[C * D];
__device__ int      g_counts[C];
__device__ unsigned g_done;

// ---------------- bulk async copy + mbarrier helpers ----------------
__device__ __forceinline__ unsigned s2u(const void* p) {
    return (unsigned)__cvta_generic_to_shared(p);
}
__device__ __forceinline__ void bulk_cp(void* s, const void* g, unsigned bytes, unsigned mbar) {
    asm volatile("cp.async.bulk.shared::cluster.global.mbarrier::complete_tx::bytes "
                 "[%0], [%1], %2, [%3];\n"
                 :: "r"(s2u(s)), "l"(g), "r"(bytes), "r"(mbar) : "memory");
}
__device__ __forceinline__ void mbar_init(unsigned mbar, unsigned cnt) {
    asm volatile("mbarrier.init.shared.b64 [%0], %1;\n" :: "r"(mbar), "r"(cnt) : "memory");
}
__device__ __forceinline__ void mbar_expect(unsigned mbar, unsigned tx) {
    asm volatile("mbarrier.arrive.expect_tx.shared.b64 _, [%0], %1;\n"
                 :: "r"(mbar), "r"(tx) : "memory");
}
__device__ __forceinline__ void mbar_wait(unsigned mbar, unsigned ph) {
    unsigned done;
    asm volatile("{\n\t.reg .pred p;\n\t"
                 "mbarrier.try_wait.parity.acquire.cta.shared::cta.b64 p, [%1], %2;\n\t"
                 "selp.b32 %0, 1, 0, p;\n\t}"
                 : "=r"(done) : "r"(mbar), "r"(ph) : "memory");
    if (!done) {
        asm volatile("{\n\t.reg .pred P1;\n\t"
                     "WL_%=:\n\t"
                     "mbarrier.try_wait.parity.acquire.cta.shared::cta.b64 P1, [%0], %1, 0x989680;\n\t"
                     "@P1 bra.uni WD_%=;\n\t"
                     "bra.uni WL_%=;\n\t"
                     "WD_%=:\n\t}"
                     :: "r"(mbar), "r"(ph) : "memory");
    }
}

// ---------------- smem layout (floats) ----------------
// buf   : 2 * D * P   = 32768 (128 KB)  double-buffered tile [d][64]
// slab  : 2 * P       = 128            labels
// acc   : 2 * C * D   = 10752 (43 KB)  two accumulator copies
// nred  : TPB         = 512            scalar partial squares
// aux   : P           = 64             packed (lab*D)<<16 | half(invnorm)
// scnt  : 32          = 32
// mbar  : 4           = 2 x 8B mbarriers
#define SM_BUF   0
#define SM_SLAB  (2*D*P)
#define SM_ACC   (SM_SLAB + 2*P)
#define SM_NRED  (SM_ACC + 2*C*D)
#define SM_AUX   (SM_NRED + TPB)
#define SM_SCNT  (SM_AUX + P)
#define SM_MBAR  (SM_SCNT + 32)
#define SM_TOTAL_FLOATS (SM_MBAR + 8)
#define SMEM_BYTES (SM_TOTAL_FLOATS * 4)

#define TILE_TX (D * P * 4 + P * 4)   // 65536 + 256 bytes

// issue all bulk copies for tile `tile` into buffer b (threads cooperate)
__device__ __forceinline__ void issue_tile(const float* __restrict__ feat,
                                           const int* __restrict__ lab,
                                           float* buf, int* slab, unsigned mbar_b,
                                           int b, int tile, int t) {
    const int p0 = tile * P;
    if (t == 511) mbar_expect(mbar_b, TILE_TX);
    if (t < D) {          // one 256B row per dim
        bulk_cp(buf + b * (D * P) + t * P, feat + (size_t)t * N_PIX + p0, P * 4, mbar_b);
    } else if (t == D) {  // labels row
        bulk_cp(slab + b * P, lab + p0, P * 4, mbar_b);
    }
}

// ---------------- single fused kernel ----------------
__global__ __launch_bounds__(TPB, 1)
void fused_kernel(const float* __restrict__ feat, const int* __restrict__ lab,
                  const float* __restrict__ proto, float* __restrict__ out) {
    extern __shared__ float smem[];
    float*    buf  = smem + SM_BUF;
    int*      slab = (int*)(smem + SM_SLAB);
    float*    acc  = smem + SM_ACC;
    float*    nred = smem + SM_NRED;
    unsigned* aux  = (unsigned*)(smem + SM_AUX);
    int*      scnt = (int*)(smem + SM_SCNT);
    const unsigned mbar0 = s2u(smem + SM_MBAR);

    const int t = threadIdx.x;

    for (int i = t; i < 2 * C * D; i += TPB) acc[i] = 0.f;
    if (t < C) scnt[t] = 0;
    if (t == 0) {
        mbar_init(mbar0, 1);
        mbar_init(mbar0 + 8, 1);
        asm volatile("fence.proxy.async.shared::cta;\n" ::: "memory");
    }
    __syncthreads();

    int tl = blockIdx.x;
    issue_tile(feat, lab, buf, slab, mbar0, 0, tl, t);

    const int dim = t & (D - 1);     // 0..255
    const int s   = t >> 8;          // thread-set 0/1
    float* ac = acc + s * (C * D);
    const int pss = t & (P - 1);     // SS pass pixel
    const int qss = t >> 6;          // SS pass dim-octet (0..7)

    int k = 0;
    for (; tl < NTILES; tl += GRID, k++) {
        const int b  = k & 1;
        const unsigned ph = (k >> 1) & 1u;

        int nxt = tl + GRID;
        if (nxt < NTILES)
            issue_tile(feat, lab, buf, slab, mbar0 + 8 * (b ^ 1), b ^ 1, nxt, t);

        mbar_wait(mbar0 + 8 * b, ph);       // per-thread acquire wait (no bar needed)

        const float* tbase = buf + b * (D * P);
        const int*   lb    = slab + b * P;

        // ---- per-pixel sum of squares: 8 threads per pixel, 32 dims each ----
        {
            float ss = 0.f;
            #pragma unroll
            for (int dd = 0; dd < 32; dd++) {
                float v = tbase[(qss * 32 + dd) * P + pss];
                ss += v * v;
            }
            nred[t] = ss;
        }
        __syncthreads();
        if (t < P) {
            float ssum = 0.f;
            #pragma unroll
            for (int q = 0; q < 8; q++) ssum += nred[q * P + t];
            float inv = 1.0f / fmaxf(sqrtf(ssum), 1e-12f);
            int labv = lb[t];
            aux[t] = ((unsigned)(labv * D) << 16) |
                     (unsigned)__half_as_ushort(__float2half_rn(inv));
            atomicAdd(&scnt[labv], 1);
        }
        __syncthreads();

        // ---- scatter-accumulate: thread owns dim, set s owns 32 pixels ----
        {
            const float* tb = tbase + dim * P;
            #pragma unroll
            for (int i = 0; i < 32; i++) {
                int p = ((dim + i) & 31) | (s << 5);      // lane-staggered, conflict-free
                unsigned a = aux[p];
                float w = __half2float(__ushort_as_half((unsigned short)(a & 0xffffu)));
                int cb = (int)(a >> 16);                   // lab * D
                ac[cb + dim] += tb[p] * w;
            }
        }
        __syncthreads();
    }

    // ---- flush per-block partials ----
    for (int i = t; i < C * D; i += TPB)
        atomicAdd(&g_sums[i], acc[i] + acc[C * D + i]);
    if (t < C) atomicAdd(&g_counts[t], scnt[t]);
    __syncthreads();

    // ---- last block does the finalize ----
    __shared__ unsigned s_last;
    if (t == 0) {
        __threadfence();
        s_last = (atomicAdd(&g_done, 1u) == GRID - 1) ? 1u : 0u;
    }
    __syncthreads();
    if (!s_last) return;

    float* s_mean  = smem;                 // C*D
    float* s_proto = smem + C * D;         // C*D
    float* s_logit = smem + 2 * C * D;     // C*C

    for (int i = t; i < C * D; i += TPB) {
        int c = i / D;
        float cnt = (float)g_counts[c];
        s_mean[i]  = g_sums[i] / fmaxf(cnt, 1.0f);
        s_proto[i] = proto[i];
    }
    __syncthreads();

    int w = t >> 5, l = t & 31;
    for (int r = w; r < C; r += TPB / 32) {
        for (int j = 0; j < C; j++) {
            float sacc = 0.f;
            #pragma unroll
            for (int kk = 0; kk < 8; kk++)
                sacc += s_mean[r * D + l + 32 * kk] * s_proto[j * D + l + 32 * kk];
            #pragma unroll
            for (int o = 16; o; o >>= 1) sacc += __shfl_xor_sync(0xffffffffu, sacc, o);
            if (l == 0) s_logit[r * C + j] = sacc * 10.0f;   // / TEMP (0.1)
        }
    }
    __syncthreads();

    if (t < 32) {
        float v = 0.f;
        if (t >= 1 && t < C) {
            float mx = -INFINITY;
            for (int j = 0; j < C; j++) mx = fmaxf(mx, s_logit[t * C + j]);
            float den = 0.f;
            for (int j = 1; j < C; j++) den += expf(s_logit[t * C + j] - mx);
            v = logf(den) - (s_logit[t * C + t] - mx);
        }
        #pragma unroll
        for (int o = 16; o; o >>= 1) v += __shfl_xor_sync(0xffffffffu, v, o);
        if (t == 0) out[0] = v / (float)(C - 1);
    }
    __syncthreads();

    // ---- reset globals for next graph replay ----
    for (int i = t; i < C * D; i += TPB) g_sums[i] = 0.f;
    if (t < C) g_counts[t] = 0;
    if (t == 0) g_done = 0;
}

// ---------------- launch ----------------
extern "C" void kernel_launch(void* const* d_in, const int* in_sizes, int n_in,
                              void* d_out, int out_size) {
    const float* feat  = (const float*)d_in[0];   // [1,256,768,768]
    const float* proto = (const float*)d_in[1];   // [21,256]
    // d_in[2] = outputs (unused by the loss)
    const int*   lab   = (const int*)d_in[3];     // [1,1,768,768]
    float* out = (float*)d_out;

    cudaFuncSetAttribute(fused_kernel,
                         cudaFuncAttributeMaxDynamicSharedMemorySize, SMEM_BYTES);

    fused_kernel<<<GRID, TPB, SMEM_BYTES>>>(feat, lab, proto, out);
}

// round 6
// speedup vs baseline: 1.1447x; 1.1380x over previous
#include <cuda_runtime.h>
#include <math.h>

#define N_PIX (768*768)          // 589824 pixels
#define D     256
#define C     21
#define P     64                 // pixels per tile
#define NTILES (N_PIX / P)       // 9216
#define TPB   512
#define GRID  148
#define PITCH 68                 // floats per tile row (bank-conflict-free)
#define PITCH4 (PITCH/4)

// ---------------- global scratch (static, zero-initialized at load) ----------------
__device__ float    g_sums[C * D];
__device__ int      g_counts[C];
__device__ unsigned g_done;

// ---------------- bulk async copy + mbarrier helpers ----------------
__device__ __forceinline__ unsigned s2u(const void* p) {
    return (unsigned)__cvta_generic_to_shared(p);
}
__device__ __forceinline__ void bulk_cp(void* s, const void* g, unsigned bytes, unsigned mbar) {
    asm volatile("cp.async.bulk.shared::cluster.global.mbarrier::complete_tx::bytes "
                 "[%0], [%1], %2, [%3];\n"
                 :: "r"(s2u(s)), "l"(g), "r"(bytes), "r"(mbar) : "memory");
}
__device__ __forceinline__ void mbar_init(unsigned mbar, unsigned cnt) {
    asm volatile("mbarrier.init.shared.b64 [%0], %1;\n" :: "r"(mbar), "r"(cnt) : "memory");
}
__device__ __forceinline__ void mbar_expect(unsigned mbar, unsigned tx) {
    asm volatile("mbarrier.arrive.expect_tx.shared.b64 _, [%0], %1;\n"
                 :: "r"(mbar), "r"(tx) : "memory");
}
__device__ __forceinline__ void mbar_wait(unsigned mbar, unsigned ph) {
    unsigned done;
    asm volatile("{\n\t.reg .pred p;\n\t"
                 "mbarrier.try_wait.parity.acquire.cta.shared::cta.b64 p, [%1], %2;\n\t"
                 "selp.b32 %0, 1, 0, p;\n\t}"
                 : "=r"(done) : "r"(mbar), "r"(ph) : "memory");
    if (!done) {
        asm volatile("{\n\t.reg .pred P1;\n\t"
                     "WL_%=:\n\t"
                     "mbarrier.try_wait.parity.acquire.cta.shared::cta.b64 P1, [%0], %1, 0x989680;\n\t"
                     "@P1 bra.uni WD_%=;\n\t"
                     "bra.uni WL_%=;\n\t"
                     "WD_%=:\n\t}"
                     :: "r"(mbar), "r"(ph) : "memory");
    }
}

// ---------------- tf32 helpers ----------------
__device__ __forceinline__ unsigned f2tf32(float f) {
    unsigned r;
    asm("cvt.rna.tf32.f32 %0, %1;" : "=r"(r) : "f"(f));
    return r;
}
__device__ __forceinline__ void mma_tf32(float c[4], unsigned a0, unsigned a1,
                                         unsigned a2, unsigned a3,
                                         unsigned b0, unsigned b1) {
    asm volatile("mma.sync.aligned.m16n8k8.row.col.f32.tf32.tf32.f32 "
                 "{%0,%1,%2,%3}, {%4,%5,%6,%7}, {%8,%9}, {%0,%1,%2,%3};\n"
                 : "+f"(c[0]), "+f"(c[1]), "+f"(c[2]), "+f"(c[3])
                 : "r"(a0), "r"(a1), "r"(a2), "r"(a3), "r"(b0), "r"(b1));
}

// ---------------- smem layout (floats) ----------------
// buf  : 2 * D * 68 = 34816 (136 KB)  double-buffered tile, pitch-68 rows
// slab : 2 * 64     = 128             labels
// nred : 2048                         float4 partial squares
// labi : 64 / invf : 64 / scnt : 32 / mbar : 4
#define SM_BUF   0
#define SM_SLAB  (2*D*PITCH)
#define SM_NRED  (SM_SLAB + 2*P)
#define SM_LAB   (SM_NRED + 2048)
#define SM_INV   (SM_LAB + P)
#define SM_SCNT  (SM_INV + P)
#define SM_MBAR  (SM_SCNT + 32)
#define SM_TOTAL_FLOATS (SM_MBAR + 8)
#define SMEM_BYTES (SM_TOTAL_FLOATS * 4)

#define TILE_TX ((D + 1) * P * 4)     // 257 * 256 bytes

__device__ __forceinline__ void issue_tile(const float* __restrict__ feat,
                                           const int* __restrict__ lab,
                                           float* buf, int* slab, unsigned mbar_b,
                                           int b, int tile, int t) {
    const int p0 = tile * P;
    if (t == 511) mbar_expect(mbar_b, TILE_TX);
    if (t < D) {
        bulk_cp(buf + b * (D * PITCH) + t * PITCH, feat + (size_t)t * N_PIX + p0,
                P * 4, mbar_b);
    } else if (t == D) {
        bulk_cp(slab + b * P, lab + p0, P * 4, mbar_b);
    }
}

// ---------------- single fused kernel ----------------
__global__ __launch_bounds__(TPB, 1)
void fused_kernel(const float* __restrict__ feat, const int* __restrict__ lab,
                  const float* __restrict__ proto, float* __restrict__ out) {
    extern __shared__ float smem[];
    float* buf  = smem + SM_BUF;
    int*   slab = (int*)(smem + SM_SLAB);
    float* nred = smem + SM_NRED;
    int*   labi = (int*)(smem + SM_LAB);
    float* invf = smem + SM_INV;
    int*   scnt = (int*)(smem + SM_SCNT);
    const unsigned mbar0 = s2u(smem + SM_MBAR);

    const int t = threadIdx.x;
    const int l = t & 31, w = t >> 5;        // lane, warp
    const int g = l >> 2, tk = l & 3;        // MMA group / thread-in-group

    if (t < C) scnt[t] = 0;
    if (t == 0) {
        mbar_init(mbar0, 1);
        mbar_init(mbar0 + 8, 1);
        asm volatile("fence.proxy.async.shared::cta;\n" ::: "memory");
    }
    __syncthreads();

    int tl = blockIdx.x;
    issue_tile(feat, lab, buf, slab, mbar0, 0, tl, t);

    const int p4 = t & 15;                   // SS pass: pixel quad
    const int q  = t >> 4;                   // SS pass: dim-octet (0..31)

    float acc[4][4];                         // persistent per-thread accumulators
    #pragma unroll
    for (int n = 0; n < 4; n++)
        #pragma unroll
        for (int i = 0; i < 4; i++) acc[n][i] = 0.f;

    int k = 0;
    for (; tl < NTILES; tl += GRID, k++) {
        const int b  = k & 1;
        const unsigned ph = (k >> 1) & 1u;

        int nxt = tl + GRID;
        if (nxt < NTILES)
            issue_tile(feat, lab, buf, slab, mbar0 + 8 * (b ^ 1), b ^ 1, nxt, t);

        mbar_wait(mbar0 + 8 * b, ph);

        const float* tbase = buf + b * (D * PITCH);
        const int*   lb    = slab + b * P;

        // ---- per-pixel sum of squares (float4, conflict-free) ----
        {
            const float4* tb4 = (const float4*)tbase;
            float4 ss = make_float4(0.f, 0.f, 0.f, 0.f);
            #pragma unroll
            for (int j = 0; j < 8; j++) {
                float4 v = tb4[(q * 8 + j) * PITCH4 + p4];
                ss.x += v.x * v.x; ss.y += v.y * v.y;
                ss.z += v.z * v.z; ss.w += v.w * v.w;
            }
            ((float4*)nred)[q * 16 + p4] = ss;
        }
        __syncthreads();
        if (t < P) {
            float ssum = 0.f;
            #pragma unroll
            for (int qq = 0; qq < 32; qq++) ssum += nred[qq * 64 + t];
            float inv = 1.0f / fmaxf(sqrtf(ssum), 1e-12f);
            int labv = lb[t];
            labi[t] = labv;
            invf[t] = __uint_as_float(f2tf32(inv));  // pre-rounded to tf32
            atomicAdd(&scnt[labv], 1);
        }
        __syncthreads();

        // ---- MMA: OUT[dim, class] += F[dim, pix] @ W[pix, class] ----
        {
            const float* ar0 = tbase + (16 * w + g) * PITCH;
            const float* ar1 = ar0 + 8 * PITCH;
            #pragma unroll
            for (int k0 = 0; k0 < P; k0 += 8) {
                unsigned a0 = f2tf32(ar0[k0 + tk]);
                unsigned a1 = f2tf32(ar1[k0 + tk]);
                unsigned a2 = f2tf32(ar0[k0 + tk + 4]);
                unsigned a3 = f2tf32(ar1[k0 + tk + 4]);
                int   lb1 = labi[k0 + tk],     lb2 = labi[k0 + tk + 4];
                unsigned in1 = __float_as_uint(invf[k0 + tk]);
                unsigned in2 = __float_as_uint(invf[k0 + tk + 4]);
                #pragma unroll
                for (int n = 0; n < 4; n++) {
                    int cls = 8 * n + g;
                    unsigned b0 = (lb1 == cls) ? in1 : 0u;
                    unsigned b1 = (lb2 == cls) ? in2 : 0u;
                    mma_tf32(acc[n], a0, a1, a2, a3, b0, b1);
                }
            }
        }
        __syncthreads();
    }

    // ---- flush register accumulators ----
    {
        const int dimA = 16 * w + g;
        const int dimB = dimA + 8;
        #pragma unroll
        for (int n = 0; n < 4; n++) {
            int cls0 = 8 * n + 2 * tk;
            int cls1 = cls0 + 1;
            if (cls0 < C) {
                atomicAdd(&g_sums[cls0 * D + dimA], acc[n][0]);
                atomicAdd(&g_sums[cls0 * D + dimB], acc[n][2]);
            }
            if (cls1 < C) {
                atomicAdd(&g_sums[cls1 * D + dimA], acc[n][1]);
                atomicAdd(&g_sums[cls1 * D + dimB], acc[n][3]);
            }
        }
    }
    if (t < C) atomicAdd(&g_counts[t], scnt[t]);
    __syncthreads();

    // ---- last block does the finalize ----
    __shared__ unsigned s_last;
    if (t == 0) {
        __threadfence();
        s_last = (atomicAdd(&g_done, 1u) == GRID - 1) ? 1u : 0u;
    }
    __syncthreads();
    if (!s_last) return;

    float* s_mean  = smem;                 // C*D
    float* s_proto = smem + C * D;         // C*D
    float* s_logit = smem + 2 * C * D;     // C*C

    for (int i = t; i < C * D; i += TPB) {
        int c = i / D;
        float cnt = (float)g_counts[c];
        s_mean[i]  = g_sums[i] / fmaxf(cnt, 1.0f);
        s_proto[i] = proto[i];
    }
    __syncthreads();

    for (int r = w; r < C; r += TPB / 32) {
        for (int j = 0; j < C; j++) {
            float sacc = 0.f;
            #pragma unroll
            for (int kk = 0; kk < 8; kk++)
                sacc += s_mean[r * D + l + 32 * kk] * s_proto[j * D + l + 32 * kk];
            #pragma unroll
            for (int o = 16; o; o >>= 1) sacc += __shfl_xor_sync(0xffffffffu, sacc, o);
            if (l == 0) s_logit[r * C + j] = sacc * 10.0f;   // / TEMP (0.1)
        }
    }
    __syncthreads();

    if (t < 32) {
        float v = 0.f;
        if (t >= 1 && t < C) {
            float mx = -INFINITY;
            for (int j = 0; j < C; j++) mx = fmaxf(mx, s_logit[t * C + j]);
            float den = 0.f;
            for (int j = 1; j < C; j++) den += expf(s_logit[t * C + j] - mx);
            v = logf(den) - (s_logit[t * C + t] - mx);
        }
        #pragma unroll
        for (int o = 16; o; o >>= 1) v += __shfl_xor_sync(0xffffffffu, v, o);
        if (t == 0) out[0] = v / (float)(C - 1);
    }
    __syncthreads();

    // ---- reset globals for next graph replay ----
    for (int i = t; i < C * D; i += TPB) g_sums[i] = 0.f;
    if (t < C) g_counts[t] = 0;
    if (t == 0) g_done = 0;
}

// ---------------- launch ----------------
extern "C" void kernel_launch(void* const* d_in, const int* in_sizes, int n_in,
                              void* d_out, int out_size) {
    const float* feat  = (const float*)d_in[0];   // [1,256,768,768]
    const float* proto = (const float*)d_in[1];   // [21,256]
    // d_in[2] = outputs (unused by the loss)
    const int*   lab   = (const int*)d_in[3];     // [1,1,768,768]
    float* out = (float*)d_out;

    cudaFuncSetAttribute(fused_kernel,
                         cudaFuncAttributeMaxDynamicSharedMemorySize, SMEM_BYTES);

    fused_kernel<<<GRID, TPB, SMEM_BYTES>>>(feat, lab, proto, out);
}

// round 7
// speedup vs baseline: 1.1450x; 1.0002x over previous
#include <cuda_runtime.h>
#include <math.h>

#define N_PIX (768*768)          // 589824 pixels
#define D     256
#define C     21
#define P     64                 // pixels per tile
#define NTILES (N_PIX / P)       // 9216
#define TPB   512
#define GRID  148
#define PITCH 68                 // floats per tile row (bank-conflict-free)
#define PITCH4 (PITCH/4)

// ---------------- global scratch (static, zero-initialized at load) ----------------
__device__ float    g_sums[C * D];
__device__ int      g_counts[C];
__device__ unsigned g_done;

// ---------------- bulk async copy + mbarrier helpers ----------------
__device__ __forceinline__ unsigned s2u(const void* p) {
    return (unsigned)__cvta_generic_to_shared(p);
}
__device__ __forceinline__ void bulk_cp(void* s, const void* g, unsigned bytes, unsigned mbar) {
    asm volatile("cp.async.bulk.shared::cluster.global.mbarrier::complete_tx::bytes "
                 "[%0], [%1], %2, [%3];\n"
                 :: "r"(s2u(s)), "l"(g), "r"(bytes), "r"(mbar) : "memory");
}
__device__ __forceinline__ void mbar_init(unsigned mbar, unsigned cnt) {
    asm volatile("mbarrier.init.shared.b64 [%0], %1;\n" :: "r"(mbar), "r"(cnt) : "memory");
}
__device__ __forceinline__ void mbar_expect(unsigned mbar, unsigned tx) {
    asm volatile("mbarrier.arrive.expect_tx.shared.b64 _, [%0], %1;\n"
                 :: "r"(mbar), "r"(tx) : "memory");
}
__device__ __forceinline__ void mbar_wait(unsigned mbar, unsigned ph) {
    unsigned done;
    asm volatile("{\n\t.reg .pred p;\n\t"
                 "mbarrier.try_wait.parity.acquire.cta.shared::cta.b64 p, [%1], %2;\n\t"
                 "selp.b32 %0, 1, 0, p;\n\t}"
                 : "=r"(done) : "r"(mbar), "r"(ph) : "memory");
    if (!done) {
        asm volatile("{\n\t.reg .pred P1;\n\t"
                     "WL_%=:\n\t"
                     "mbarrier.try_wait.parity.acquire.cta.shared::cta.b64 P1, [%0], %1, 0x989680;\n\t"
                     "@P1 bra.uni WD_%=;\n\t"
                     "bra.uni WL_%=;\n\t"
                     "WD_%=:\n\t}"
                     :: "r"(mbar), "r"(ph) : "memory");
    }
}

// ---------------- tf32 helpers ----------------
__device__ __forceinline__ unsigned f2tf32(float f) {
    unsigned r;
    asm("cvt.rna.tf32.f32 %0, %1;" : "=r"(r) : "f"(f));
    return r;
}
__device__ __forceinline__ void mma_tf32(float c[4], unsigned a0, unsigned a1,
                                         unsigned a2, unsigned a3,
                                         unsigned b0, unsigned b1) {
    asm volatile("mma.sync.aligned.m16n8k8.row.col.f32.tf32.tf32.f32 "
                 "{%0,%1,%2,%3}, {%4,%5,%6,%7}, {%8,%9}, {%0,%1,%2,%3};\n"
                 : "+f"(c[0]), "+f"(c[1]), "+f"(c[2]), "+f"(c[3])
                 : "r"(a0), "r"(a1), "r"(a2), "r"(a3), "r"(b0), "r"(b1));
}

// ---------------- smem layout (floats) ----------------
// buf  : 2 * D * 68 = 34816 (136 KB)  double-buffered tile, pitch-68 rows
// slab : 2 * 64     = 128             labels
// nred : 2048                         float4 partial squares
// labi : 64 / invf : 64 / scnt : 32 / mbar : 4
#define SM_BUF   0
#define SM_SLAB  (2*D*PITCH)
#define SM_NRED  (SM_SLAB + 2*P)
#define SM_LAB   (SM_NRED + 2048)
#define SM_INV   (SM_LAB + P)
#define SM_SCNT  (SM_INV + P)
#define SM_MBAR  (SM_SCNT + 32)
#define SM_TOTAL_FLOATS (SM_MBAR + 8)
#define SMEM_BYTES (SM_TOTAL_FLOATS * 4)

#define TILE_TX ((D + 1) * P * 4)     // 257 * 256 bytes

__device__ __forceinline__ void issue_tile(const float* __restrict__ feat,
                                           const int* __restrict__ lab,
                                           float* buf, int* slab, unsigned mbar_b,
                                           int b, int tile, int t) {
    const int p0 = tile * P;
    if (t == 511) mbar_expect(mbar_b, TILE_TX);
    if (t < D) {
        bulk_cp(buf + b * (D * PITCH) + t * PITCH, feat + (size_t)t * N_PIX + p0,
                P * 4, mbar_b);
    } else if (t == D) {
        bulk_cp(slab + b * P, lab + p0, P * 4, mbar_b);
    }
}

// ---------------- single fused kernel ----------------
__global__ __launch_bounds__(TPB, 1)
void fused_kernel(const float* __restrict__ feat, const int* __restrict__ lab,
                  const float* __restrict__ proto, float* __restrict__ out) {
    extern __shared__ float smem[];
    float* buf  = smem + SM_BUF;
    int*   slab = (int*)(smem + SM_SLAB);
    float* nred = smem + SM_NRED;
    int*   labi = (int*)(smem + SM_LAB);
    float* invf = smem + SM_INV;
    int*   scnt = (int*)(smem + SM_SCNT);
    const unsigned mbar0 = s2u(smem + SM_MBAR);

    const int t = threadIdx.x;
    const int l = t & 31, w = t >> 5;        // lane, warp
    const int g = l >> 2, tk = l & 3;        // MMA group / thread-in-group

    if (t < C) scnt[t] = 0;
    if (t == 0) {
        mbar_init(mbar0, 1);
        mbar_init(mbar0 + 8, 1);
        asm volatile("fence.proxy.async.shared::cta;\n" ::: "memory");
    }
    __syncthreads();

    int tl = blockIdx.x;
    issue_tile(feat, lab, buf, slab, mbar0, 0, tl, t);

    const int p4 = t & 15;                   // SS pass: pixel quad
    const int q  = t >> 4;                   // SS pass: dim-octet (0..31)

    float acc[4][4];                         // persistent per-thread accumulators
    #pragma unroll
    for (int n = 0; n < 4; n++)
        #pragma unroll
        for (int i = 0; i < 4; i++) acc[n][i] = 0.f;

    int k = 0;
    for (; tl < NTILES; tl += GRID, k++) {
        const int b  = k & 1;
        const unsigned ph = (k >> 1) & 1u;

        int nxt = tl + GRID;
        if (nxt < NTILES)
            issue_tile(feat, lab, buf, slab, mbar0 + 8 * (b ^ 1), b ^ 1, nxt, t);

        mbar_wait(mbar0 + 8 * b, ph);

        const float* tbase = buf + b * (D * PITCH);
        const int*   lb    = slab + b * P;

        // ---- per-pixel sum of squares (float4, conflict-free) ----
        {
            const float4* tb4 = (const float4*)tbase;
            float4 ss = make_float4(0.f, 0.f, 0.f, 0.f);
            #pragma unroll
            for (int j = 0; j < 8; j++) {
                float4 v = tb4[(q * 8 + j) * PITCH4 + p4];
                ss.x += v.x * v.x; ss.y += v.y * v.y;
                ss.z += v.z * v.z; ss.w += v.w * v.w;
            }
            ((float4*)nred)[q * 16 + p4] = ss;
        }
        __syncthreads();
        if (t < P) {
            float ssum = 0.f;
            #pragma unroll
            for (int qq = 0; qq < 32; qq++) ssum += nred[qq * 64 + t];
            float inv = 1.0f / fmaxf(sqrtf(ssum), 1e-12f);
            int labv = lb[t];
            labi[t] = labv;
            invf[t] = __uint_as_float(f2tf32(inv));  // pre-rounded to tf32
            atomicAdd(&scnt[labv], 1);
        }
        __syncthreads();

        // ---- MMA: OUT[dim, class] += F[dim, pix] @ W[pix, class] ----
        {
            const float* ar0 = tbase + (16 * w + g) * PITCH;
            const float* ar1 = ar0 + 8 * PITCH;
            #pragma unroll
            for (int k0 = 0; k0 < P; k0 += 8) {
                unsigned a0 = f2tf32(ar0[k0 + tk]);
                unsigned a1 = f2tf32(ar1[k0 + tk]);
                unsigned a2 = f2tf32(ar0[k0 + tk + 4]);
                unsigned a3 = f2tf32(ar1[k0 + tk + 4]);
                int   lb1 = labi[k0 + tk],     lb2 = labi[k0 + tk + 4];
                unsigned in1 = __float_as_uint(invf[k0 + tk]);
                unsigned in2 = __float_as_uint(invf[k0 + tk + 4]);
                #pragma unroll
                for (int n = 0; n < 4; n++) {
                    int cls = 8 * n + g;
                    unsigned b0 = (lb1 == cls) ? in1 : 0u;
                    unsigned b1 = (lb2 == cls) ? in2 : 0u;
                    mma_tf32(acc[n], a0, a1, a2, a3, b0, b1);
                }
            }
        }
        __syncthreads();
    }

    // ---- flush register accumulators ----
    {
        const int dimA = 16 * w + g;
        const int dimB = dimA + 8;
        #pragma unroll
        for (int n = 0; n < 4; n++) {
            int cls0 = 8 * n + 2 * tk;
            int cls1 = cls0 + 1;
            if (cls0 < C) {
                atomicAdd(&g_sums[cls0 * D + dimA], acc[n][0]);
                atomicAdd(&g_sums[cls0 * D + dimB], acc[n][2]);
            }
            if (cls1 < C) {
                atomicAdd(&g_sums[cls1 * D + dimA], acc[n][1]);
                atomicAdd(&g_sums[cls1 * D + dimB], acc[n][3]);
            }
        }
    }
    if (t < C) atomicAdd(&g_counts[t], scnt[t]);
    __syncthreads();

    // ---- last block does the finalize ----
    __shared__ unsigned s_last;
    if (t == 0) {
        __threadfence();
        s_last = (atomicAdd(&g_done, 1u) == GRID - 1) ? 1u : 0u;
    }
    __syncthreads();
    if (!s_last) return;

    float* s_mean  = smem;                 // C*D
    float* s_proto = smem + C * D;         // C*D
    float* s_logit = smem + 2 * C * D;     // C*C

    for (int i = t; i < C * D; i += TPB) {
        int c = i / D;
        float cnt = (float)g_counts[c];
        s_mean[i]  = g_sums[i] / fmaxf(cnt, 1.0f);
        s_proto[i] = proto[i];
    }
    __syncthreads();

    for (int r = w; r < C; r += TPB / 32) {
        for (int j = 0; j < C; j++) {
            float sacc = 0.f;
            #pragma unroll
            for (int kk = 0; kk < 8; kk++)
                sacc += s_mean[r * D + l + 32 * kk] * s_proto[j * D + l + 32 * kk];
            #pragma unroll
            for (int o = 16; o; o >>= 1) sacc += __shfl_xor_sync(0xffffffffu, sacc, o);
            if (l == 0) s_logit[r * C + j] = sacc * 10.0f;   // / TEMP (0.1)
        }
    }
    __syncthreads();

    if (t < 32) {
        float v = 0.f;
        if (t >= 1 && t < C) {
            float mx = -INFINITY;
            for (int j = 0; j < C; j++) mx = fmaxf(mx, s_logit[t * C + j]);
            float den = 0.f;
            for (int j = 1; j < C; j++) den += expf(s_logit[t * C + j] - mx);
            v = logf(den) - (s_logit[t * C + t] - mx);
        }
        #pragma unroll
        for (int o = 16; o; o >>= 1) v += __shfl_xor_sync(0xffffffffu, v, o);
        if (t == 0) out[0] = v / (float)(C - 1);
    }
    __syncthreads();

    // ---- reset globals for next graph replay ----
    for (int i = t; i < C * D; i += TPB) g_sums[i] = 0.f;
    if (t < C) g_counts[t] = 0;
    if (t == 0) g_done = 0;
}

// ---------------- launch ----------------
extern "C" void kernel_launch(void* const* d_in, const int* in_sizes, int n_in,
                              void* d_out, int out_size) {
    const float* feat  = (const float*)d_in[0];   // [1,256,768,768]
    const float* proto = (const float*)d_in[1];   // [21,256]
    // d_in[2] = outputs (unused by the loss)
    const int*   lab   = (const int*)d_in[3];     // [1,1,768,768]
    float* out = (float*)d_out;

    cudaFuncSetAttribute(fused_kernel,
                         cudaFuncAttributeMaxDynamicSharedMemorySize, SMEM_BYTES);

    fused_kernel<<<GRID, TPB, SMEM_BYTES>>>(feat, lab, proto, out);
}

// round 9
// speedup vs baseline: 1.1713x; 1.0230x over previous
#include <cuda_runtime.h>
#include <math.h>

#define N_PIX (768*768)          // 589824 pixels
#define D     256
#define C     21
#define P     64                 // pixels per tile
#define NTILES (N_PIX / P)       // 9216
#define TPB   1024
#define GRID  148
#define PITCH 68                 // floats per tile row (bank-conflict-free)
#define PITCH4 (PITCH/4)

// ---------------- global scratch (static, zero-initialized at load) ----------------
__device__ float    g_sums[C * D];
__device__ int      g_counts[C];
__device__ unsigned g_done;

// ---------------- bulk async copy + mbarrier helpers ----------------
__device__ __forceinline__ unsigned s2u(const void* p) {
    return (unsigned)__cvta_generic_to_shared(p);
}
__device__ __forceinline__ void bulk_cp(void* s, const void* g, unsigned bytes, unsigned mbar) {
    asm volatile("cp.async.bulk.shared::cluster.global.mbarrier::complete_tx::bytes "
                 "[%0], [%1], %2, [%3];\n"
                 :: "r"(s2u(s)), "l"(g), "r"(bytes), "r"(mbar) : "memory");
}
__device__ __forceinline__ void mbar_init(unsigned mbar, unsigned cnt) {
    asm volatile("mbarrier.init.shared.b64 [%0], %1;\n" :: "r"(mbar), "r"(cnt) : "memory");
}
__device__ __forceinline__ void mbar_expect(unsigned mbar, unsigned tx) {
    asm volatile("mbarrier.arrive.expect_tx.shared.b64 _, [%0], %1;\n"
                 :: "r"(mbar), "r"(tx) : "memory");
}
__device__ __forceinline__ void mbar_wait(unsigned mbar, unsigned ph) {
    unsigned done;
    asm volatile("{\n\t.reg .pred p;\n\t"
                 "mbarrier.try_wait.parity.acquire.cta.shared::cta.b64 p, [%1], %2;\n\t"
                 "selp.b32 %0, 1, 0, p;\n\t}"
                 : "=r"(done) : "r"(mbar), "r"(ph) : "memory");
    if (!done) {
        asm volatile("{\n\t.reg .pred P1;\n\t"
                     "WL_%=:\n\t"
                     "mbarrier.try_wait.parity.acquire.cta.shared::cta.b64 P1, [%0], %1, 0x989680;\n\t"
                     "@P1 bra.uni WD_%=;\n\t"
                     "bra.uni WL_%=;\n\t"
                     "WD_%=:\n\t}"
                     :: "r"(mbar), "r"(ph) : "memory");
    }
}

// ---------------- tf32 helpers ----------------
__device__ __forceinline__ unsigned f2tf32(float f) {
    unsigned r;
    asm("cvt.rna.tf32.f32 %0, %1;" : "=r"(r) : "f"(f));
    return r;
}
__device__ __forceinline__ void mma_tf32(float c[4], unsigned a0, unsigned a1,
                                         unsigned a2, unsigned a3,
                                         unsigned b0, unsigned b1) {
    asm volatile("mma.sync.aligned.m16n8k8.row.col.f32.tf32.tf32.f32 "
                 "{%0,%1,%2,%3}, {%4,%5,%6,%7}, {%8,%9}, {%0,%1,%2,%3};\n"
                 : "+f"(c[0]), "+f"(c[1]), "+f"(c[2]), "+f"(c[3])
                 : "r"(a0), "r"(a1), "r"(a2), "r"(a3), "r"(b0), "r"(b1));
}

// ---------------- smem layout (floats) ----------------
// buf  : 2 * D * 68 = 34816 (136 KB)  double-buffered tile, pitch-68 rows
// slab : 2 * 64     = 128             labels
// nred : 64*64      = 4096            partial squares [q][p]
// aux2 : 64 float2  = 128             (invnorm_tf32, label) per pixel
// scnt : 32 / mbar : 8
#define SM_BUF   0
#define SM_SLAB  (2*D*PITCH)
#define SM_NRED  (SM_SLAB + 2*P)
#define SM_AUX   (SM_NRED + 4096)
#define SM_SCNT  (SM_AUX + 2*P)
#define SM_MBAR  (SM_SCNT + 32)
#define SM_TOTAL_FLOATS (SM_MBAR + 8)
#define SMEM_BYTES (SM_TOTAL_FLOATS * 4)

#define TILE_TX ((D + 1) * P * 4)     // 257 * 256 bytes

__device__ __forceinline__ void issue_tile(const float* __restrict__ feat,
                                           const int* __restrict__ lab,
                                           float* buf, int* slab, unsigned mbar_b,
                                           int b, int tile, int t) {
    const int p0 = tile * P;
    if (t == TPB - 1) mbar_expect(mbar_b, TILE_TX);
    if (t < D) {
        bulk_cp(buf + b * (D * PITCH) + t * PITCH, feat + (size_t)t * N_PIX + p0,
                P * 4, mbar_b);
    } else if (t == D) {
        bulk_cp(slab + b * P, lab + p0, P * 4, mbar_b);
    }
}

// ---------------- single fused kernel ----------------
__global__ __launch_bounds__(TPB, 1)
void fused_kernel(const float* __restrict__ feat, const int* __restrict__ lab,
                  const float* __restrict__ proto, float* __restrict__ out) {
    extern __shared__ float smem[];
    float*  buf  = smem + SM_BUF;
    int*    slab = (int*)(smem + SM_SLAB);
    float*  nred = smem + SM_NRED;
    float2* aux2 = (float2*)(smem + SM_AUX);
    int*    scnt = (int*)(smem + SM_SCNT);
    const unsigned mbar0 = s2u(smem + SM_MBAR);

    const int t = threadIdx.x;
    const int l = t & 31, w = t >> 5;        // lane, warp (0..31)
    const int g = l >> 2, tk = l & 3;        // MMA group / thread-in-group

    if (t < C) scnt[t] = 0;
    if (t == 0) {
        mbar_init(mbar0, 1);
        mbar_init(mbar0 + 8, 1);
        asm volatile("fence.proxy.async.shared::cta;\n" ::: "memory");
    }
    __syncthreads();

    int tl = blockIdx.x;
    issue_tile(feat, lab, buf, slab, mbar0, 0, tl, t);

    const int p4 = t & 15;                   // SS pass: pixel quad 0..15
    const int q  = t >> 4;                   // SS pass: dim-quad 0..63 (4 dims each)

    // MMA ownership: dim block = 16*(w>>1), pixel half = (w&1)*32
    const int dim0  = 16 * (w >> 1);
    const int kbase = (w & 1) * 32;

    float acc[4][4];                         // persistent per-thread accumulators
    #pragma unroll
    for (int n = 0; n < 4; n++)
        #pragma unroll
        for (int i = 0; i < 4; i++) acc[n][i] = 0.f;

    int k = 0;
    for (; tl < NTILES; tl += GRID, k++) {
        const int b  = k & 1;
        const unsigned ph = (k >> 1) & 1u;

        int nxt = tl + GRID;
        if (nxt < NTILES)
            issue_tile(feat, lab, buf, slab, mbar0 + 8 * (b ^ 1), b ^ 1, nxt, t);

        mbar_wait(mbar0 + 8 * b, ph);

        const float* tbase = buf + b * (D * PITCH);
        const int*   lb    = slab + b * P;

        // ---- per-pixel sum of squares: 1024 threads, 4 dims each ----
        {
            const float4* tb4 = (const float4*)tbase;
            float4 ss = make_float4(0.f, 0.f, 0.f, 0.f);
            #pragma unroll
            for (int j = 0; j < 4; j++) {
                float4 v = tb4[(q * 4 + j) * PITCH4 + p4];
                ss.x += v.x * v.x; ss.y += v.y * v.y;
                ss.z += v.z * v.z; ss.w += v.w * v.w;
            }
            ((float4*)nred)[q * 16 + p4] = ss;
        }
        __syncthreads();
        if (t < P) {
            float ssum = 0.f;
            #pragma unroll
            for (int qq = 0; qq < 64; qq++) ssum += nred[qq * 64 + t];
            float inv = 1.0f / fmaxf(sqrtf(ssum), 1e-12f);
            int labv = lb[t];
            aux2[t] = make_float2(__uint_as_float(f2tf32(inv)),
                                  __int_as_float(labv));
            atomicAdd(&scnt[labv], 1);
        }
        __syncthreads();

        // ---- MMA: OUT[dim, class] += F[dim, pix] @ W[pix, class] ----
        {
            const float* ar0 = tbase + (dim0 + g) * PITCH;
            const float* ar1 = ar0 + 8 * PITCH;
            #pragma unroll
            for (int kk = 0; kk < 4; kk++) {
                int k0 = kbase + kk * 8;
                // raw f32 bits as tf32 operands (hardware truncates mantissa)
                unsigned a0 = __float_as_uint(ar0[k0 + tk]);
                unsigned a1 = __float_as_uint(ar1[k0 + tk]);
                unsigned a2 = __float_as_uint(ar0[k0 + tk + 4]);
                unsigned a3 = __float_as_uint(ar1[k0 + tk + 4]);
                float2 x1 = aux2[k0 + tk];
                float2 x2 = aux2[k0 + tk + 4];
                int lb1 = __float_as_int(x1.y), lb2 = __float_as_int(x2.y);
                unsigned in1 = __float_as_uint(x1.x), in2 = __float_as_uint(x2.x);
                #pragma unroll
                for (int n = 0; n < 4; n++) {
                    int cls = 8 * n + g;
                    unsigned b0 = (lb1 == cls) ? in1 : 0u;
                    unsigned b1 = (lb2 == cls) ? in2 : 0u;
                    mma_tf32(acc[n], a0, a1, a2, a3, b0, b1);
                }
            }
        }
        __syncthreads();
    }

    // ---- flush register accumulators (two k-half warps merge via atomics) ----
    {
        const int dimA = dim0 + g;
        const int dimB = dimA + 8;
        #pragma unroll
        for (int n = 0; n < 4; n++) {
            int cls0 = 8 * n + 2 * tk;
            int cls1 = cls0 + 1;
            if (cls0 < C) {
                atomicAdd(&g_sums[cls0 * D + dimA], acc[n][0]);
                atomicAdd(&g_sums[cls0 * D + dimB], acc[n][2]);
            }
            if (cls1 < C) {
                atomicAdd(&g_sums[cls1 * D + dimA], acc[n][1]);
                atomicAdd(&g_sums[cls1 * D + dimB], acc[n][3]);
            }
        }
    }
    if (t < C) atomicAdd(&g_counts[t], scnt[t]);
    __syncthreads();

    // ---- last block does the finalize ----
    __shared__ unsigned s_last;
    if (t == 0) {
        __threadfence();
        s_last = (atomicAdd(&g_done, 1u) == GRID - 1) ? 1u : 0u;
    }
    __syncthreads();
    if (!s_last) return;

    float* s_mean  = smem;                 // C*D
    float* s_proto = smem + C * D;         // C*D
    float* s_logit = smem + 2 * C * D;     // C*C

    for (int i = t; i < C * D; i += TPB) {
        int c = i / D;
        float cnt = (float)g_counts[c];
        s_mean[i]  = g_sums[i] / fmaxf(cnt, 1.0f);
        s_proto[i] = proto[i];
    }
    __syncthreads();

    for (int r = w; r < C; r += TPB / 32) {
        for (int j = 0; j < C; j++) {
            float sacc = 0.f;
            #pragma unroll
            for (int kk = 0; kk < 8; kk++)
                sacc += s_mean[r * D + l + 32 * kk] * s_proto[j * D + l + 32 * kk];
            #pragma unroll
            for (int o = 16; o; o >>= 1) sacc += __shfl_xor_sync(0xffffffffu, sacc, o);
            if (l == 0) s_logit[r * C + j] = sacc * 10.0f;   // / TEMP (0.1)
        }
    }
    __syncthreads();

    if (t < 32) {
        float v = 0.f;
        if (t >= 1 && t < C) {
            float mx = -INFINITY;
            for (int j = 0; j < C; j++) mx = fmaxf(mx, s_logit[t * C + j]);
            float den = 0.f;
            for (int j = 1; j < C; j++) den += expf(s_logit[t * C + j] - mx);
            v = logf(den) - (s_logit[t * C + t] - mx);
        }
        #pragma unroll
        for (int o = 16; o; o >>= 1) v += __shfl_xor_sync(0xffffffffu, v, o);
        if (t == 0) out[0] = v / (float)(C - 1);
    }
    __syncthreads();

    // ---- reset globals for next graph replay ----
    for (int i = t; i < C * D; i += TPB) g_sums[i] = 0.f;
    if (t < C) g_counts[t] = 0;
    if (t == 0) g_done = 0;
}

// ---------------- launch ----------------
extern "C" void kernel_launch(void* const* d_in, const int* in_sizes, int n_in,
                              void* d_out, int out_size) {
    const float* feat  = (const float*)d_in[0];   // [1,256,768,768]
    const float* proto = (const float*)d_in[1];   // [21,256]
    // d_in[2] = outputs (unused by the loss)
    const int*   lab   = (const int*)d_in[3];     // [1,1,768,768]
    float* out = (float*)d_out;

    cudaFuncSetAttribute(fused_kernel,
                         cudaFuncAttributeMaxDynamicSharedMemorySize, SMEM_BYTES);

    fused_kernel<<<GRID, TPB, SMEM_BYTES>>>(feat, lab, proto, out);
}